// round 11
// baseline (speedup 1.0000x reference)
#include <cuda_runtime.h>
#include <cuda_fp16.h>

#define N_NODES 50000
#define N_EDGES 800000
#define DIM     256
#define HID     128
#define NTHR    256
#define SCAN_B  1024
#define NB_SCAN ((N_NODES + SCAN_B - 1) / SCAN_B)   // 49

#define TM      64                 // nodes per block in node_weight
#define LDK     264                // padded fp16 row stride (256 + 8)

__device__ float g_wnode[N_NODES];
__device__ int   g_is64;
__device__ int   g_cnt[N_NODES];
__device__ int   g_incl[N_NODES];
__device__ int   g_btot[64];
__device__ int   g_start[N_NODES + 1];
__device__ int   g_cur[N_NODES + 1];
__device__ int   g_scol[N_EDGES];
__device__ __align__(16) __half g_xh[N_NODES * DIM];   // fp16 mirror of x
__device__ __align__(16) __half g_w1t[HID * DIM];      // W1^T fp16: [n][k]

// ---------------------------------------------------------------------------
__device__ __forceinline__ int load_idx(const void* ei, long long pos, bool is64) {
    int v = is64 ? (int)((const long long*)ei)[pos] : ((const int*)ei)[pos];
    return min(max(v, 0), N_NODES - 1);
}

__device__ __forceinline__ void mma_f16(float* c, const unsigned* a,
                                        unsigned b0, unsigned b1) {
    asm volatile(
        "mma.sync.aligned.m16n8k16.row.col.f32.f16.f16.f32 "
        "{%0,%1,%2,%3}, {%4,%5,%6,%7}, {%8,%9}, {%0,%1,%2,%3};"
        : "+f"(c[0]), "+f"(c[1]), "+f"(c[2]), "+f"(c[3])
        : "r"(a[0]), "r"(a[1]), "r"(a[2]), "r"(a[3]), "r"(b0), "r"(b1));
}

// ---------------------------------------------------------------------------
__global__ void detect_kernel(const int* __restrict__ ei32) {
    int all_hi_zero = 1;
    #pragma unroll 8
    for (int i = 0; i < 512; ++i)
        if (ei32[2 * i + 1] != 0) { all_hi_zero = 0; break; }
    g_is64 = all_hi_zero;
}

__global__ void zero_cnt_kernel() {
    int i = blockIdx.x * blockDim.x + threadIdx.x;
    if (i < N_NODES) g_cnt[i] = 0;
}

// x -> fp16 mirror (for agg gathers)
__global__ void convert_x_kernel(const float4* __restrict__ x4) {
    const int total = N_NODES * (DIM / 4);
    int i = blockIdx.x * blockDim.x + threadIdx.x;
    if (i >= total) return;
    float4 v = __ldg(&x4[i]);
    __half2* dst = (__half2*)g_xh;
    dst[2 * i]     = __floats2half2_rn(v.x, v.y);
    dst[2 * i + 1] = __floats2half2_rn(v.z, v.w);
}

// W1 [k][n] fp32 -> W1^T fp16 [n][k], tiled transpose: coalesced on BOTH sides
// (the old version read stride-512B -- one cache line per thread).
__global__ void prep_w1_kernel(const float* __restrict__ W1) {
    __shared__ float t[32][33];
    const int bk = blockIdx.x * 32;   // k tile base (DIM/32 = 8)
    const int bn = blockIdx.y * 32;   // n tile base (HID/32 = 4)
    const int tx = threadIdx.x;       // 0..31
    const int ty = threadIdx.y;       // 0..7
    #pragma unroll
    for (int i = ty; i < 32; i += 8)
        t[i][tx] = __ldg(&W1[(bk + i) * HID + bn + tx]);   // coalesced in n
    __syncthreads();
    #pragma unroll
    for (int i = ty; i < 32; i += 8)
        g_w1t[(bn + i) * DIM + bk + tx] = __float2half_rn(t[tx][i]);  // coalesced in k
}

// ---------------------------------------------------------------------------
// CSR build
// ---------------------------------------------------------------------------
__global__ void count_kernel(const void* __restrict__ ei) {
    int e = blockIdx.x * blockDim.x + threadIdx.x;
    if (e >= N_EDGES) return;
    int row = load_idx(ei, e, g_is64 != 0);
    atomicAdd(&g_cnt[row], 1);
}

__global__ void scan1_kernel() {
    __shared__ int s_wt[32];
    const int t = threadIdx.x, b = blockIdx.x;
    const int lane = t & 31, wid = t >> 5;
    const int i = b * SCAN_B + t;
    int sv = (i < N_NODES) ? g_cnt[i] : 0;
    #pragma unroll
    for (int off = 1; off < 32; off <<= 1) {
        int u = __shfl_up_sync(0xffffffffu, sv, off);
        if (lane >= off) sv += u;
    }
    if (lane == 31) s_wt[wid] = sv;
    __syncthreads();
    if (wid == 0) {
        int wv = s_wt[lane];
        #pragma unroll
        for (int off = 1; off < 32; off <<= 1) {
            int u = __shfl_up_sync(0xffffffffu, wv, off);
            if (lane >= off) wv += u;
        }
        s_wt[lane] = wv;
    }
    __syncthreads();
    int incl = sv + ((wid > 0) ? s_wt[wid - 1] : 0);
    if (i < N_NODES) g_incl[i] = incl;
    if (t == SCAN_B - 1) g_btot[b] = incl;
}

__global__ void scan2_kernel() {
    if (threadIdx.x == 0) {
        int run = 0;
        #pragma unroll 1
        for (int b = 0; b < NB_SCAN; ++b) {
            int t = g_btot[b];
            g_btot[b] = run;
            run += t;
        }
    }
}

__global__ void scan3_kernel() {
    int i = blockIdx.x * blockDim.x + threadIdx.x;
    if (i >= N_NODES) return;
    int v = g_incl[i] + g_btot[i >> 10];
    g_start[i + 1] = v;
    g_cur[i + 1]   = v;
    if (i == 0) { g_start[0] = 0; g_cur[0] = 0; }
}

__global__ void fill_kernel(const void* __restrict__ ei) {
    int e = blockIdx.x * blockDim.x + threadIdx.x;
    if (e >= N_EDGES) return;
    bool is64 = (g_is64 != 0);
    int row = load_idx(ei, e, is64);
    int col = load_idx(ei, (long long)N_EDGES + e, is64);
    int pos = atomicAdd(&g_cur[row], 1);
    g_scol[pos] = col;
}

// ---------------------------------------------------------------------------
// Node attention weights via single-product fp16 HMMA (unchanged from R10).
// ---------------------------------------------------------------------------
__global__ __launch_bounds__(NTHR)
void node_weight_kernel(const float* __restrict__ x,
                        const float* __restrict__ b1,
                        const float* __restrict__ W2,
                        const float* __restrict__ b2)
{
    __shared__ __half sxh[TM * LDK];
    __shared__ float s_red[2][TM];
    __shared__ float s_b1[HID];
    __shared__ float s_w2[HID];

    const int tid  = threadIdx.x;
    const int lane = tid & 31;
    const int wid  = tid >> 5;
    const int wm   = wid >> 1;
    const int wn   = wid & 1;
    const int base = blockIdx.x * TM;

    if (tid < HID) {
        s_b1[tid] = __ldg(&b1[tid]);
        s_w2[tid] = __ldg(&W2[tid]);
    }

    #pragma unroll
    for (int it = 0; it < (TM * (DIM / 4)) / NTHR; ++it) {
        int f = it * NTHR + tid;
        int row = f >> 6;
        int q = f & 63;
        int node = min(base + row, N_NODES - 1);
        float4 v = __ldg(((const float4*)(x + (long long)node * DIM)) + q);
        __half2* o = (__half2*)&sxh[row * LDK + q * 4];
        o[0] = __floats2half2_rn(v.x, v.y);
        o[1] = __floats2half2_rn(v.z, v.w);
    }
    __syncthreads();

    float acc[8][4];
    #pragma unroll
    for (int nt = 0; nt < 8; ++nt)
        #pragma unroll
        for (int c = 0; c < 4; ++c) acc[nt][c] = 0.f;

    const int r0  = wm * 16 + (lane >> 2);
    const int klo = (lane & 3) * 2;
    const unsigned* W1t32 = (const unsigned*)g_w1t;

    #pragma unroll 1
    for (int ks = 0; ks < DIM / 16; ++ks) {
        const int k = ks * 16 + klo;
        unsigned a[4];
        a[0] = *(const unsigned*)&sxh[r0 * LDK + k];
        a[1] = *(const unsigned*)&sxh[(r0 + 8) * LDK + k];
        a[2] = *(const unsigned*)&sxh[r0 * LDK + k + 8];
        a[3] = *(const unsigned*)&sxh[(r0 + 8) * LDK + k + 8];

        #pragma unroll
        for (int nt = 0; nt < 8; ++nt) {
            const int n0 = wn * 64 + nt * 8 + (lane >> 2);
            const int bo = (n0 * DIM + ks * 16 + klo) >> 1;
            unsigned b0 = __ldg(&W1t32[bo]);
            unsigned b1r = __ldg(&W1t32[bo + 4]);
            mma_f16(acc[nt], a, b0, b1r);
        }
    }

    float sA = 0.f, sB = 0.f;
    #pragma unroll
    for (int nt = 0; nt < 8; ++nt) {
        int j0 = wn * 64 + nt * 8 + (lane & 3) * 2;
        float bb0 = s_b1[j0],  bb1 = s_b1[j0 + 1];
        float ww0 = s_w2[j0],  ww1 = s_w2[j0 + 1];
        sA = fmaf(fmaxf(acc[nt][0] + bb0, 0.f), ww0, sA);
        sA = fmaf(fmaxf(acc[nt][1] + bb1, 0.f), ww1, sA);
        sB = fmaf(fmaxf(acc[nt][2] + bb0, 0.f), ww0, sB);
        sB = fmaf(fmaxf(acc[nt][3] + bb1, 0.f), ww1, sB);
    }
    sA += __shfl_xor_sync(0xffffffffu, sA, 1);
    sA += __shfl_xor_sync(0xffffffffu, sA, 2);
    sB += __shfl_xor_sync(0xffffffffu, sB, 1);
    sB += __shfl_xor_sync(0xffffffffu, sB, 2);

    if ((lane & 3) == 0) {
        s_red[wn][wm * 16 + (lane >> 2)]     = sA;
        s_red[wn][wm * 16 + 8 + (lane >> 2)] = sB;
    }
    __syncthreads();

    if (tid < TM) {
        int node = base + tid;
        if (node < N_NODES) {
            float logit = s_red[0][tid] + s_red[1][tid] + __ldg(b2);
            g_wnode[node] = 1.f / (1.f + expf(-logit));
        }
    }
}

// ---------------------------------------------------------------------------
// Aggregation with depth-1 software pipeline: issue the shfl+LDG for edge c+1
// BEFORE accumulating edge c. The old loop had MLP=1 (in-order issue stalled
// on each gather before it could launch the next); this gives steady MLP~2.
// ---------------------------------------------------------------------------
__global__ __launch_bounds__(NTHR, 8)
void agg_kernel(float* __restrict__ out)
{
    const int warp = (blockIdx.x * NTHR + threadIdx.x) >> 5;
    const int lane = threadIdx.x & 31;
    if (warp >= N_NODES) return;

    const int s = g_start[warp];
    const int e = g_start[warp + 1];

    float acc[8] = {0.f, 0.f, 0.f, 0.f, 0.f, 0.f, 0.f, 0.f};
    float wsum = 0.f;

    for (int base = s; base < e; base += 32) {
        const int n = min(32, e - base);
        int   col = 0;
        float wv  = 0.f;
        if (lane < n) {
            col = g_scol[base + lane];
            wv  = __ldg(&g_wnode[col]);
        }
        // prime the pipeline with edge 0
        int   cc = __shfl_sync(0xffffffffu, col, 0);
        float ww = __shfl_sync(0xffffffffu, wv,  0);
        uint4 p  = __ldg(((const uint4*)(g_xh + (long long)cc * DIM)) + lane);

        for (int c = 0; c < n; ++c) {
            uint4 cur = p;
            float w   = ww;
            if (c + 1 < n) {   // issue next gather before consuming current
                cc = __shfl_sync(0xffffffffu, col, c + 1);
                ww = __shfl_sync(0xffffffffu, wv,  c + 1);
                p  = __ldg(((const uint4*)(g_xh + (long long)cc * DIM)) + lane);
            }
            float2 f0 = __half22float2(*(const __half2*)&cur.x);
            float2 f1 = __half22float2(*(const __half2*)&cur.y);
            float2 f2 = __half22float2(*(const __half2*)&cur.z);
            float2 f3 = __half22float2(*(const __half2*)&cur.w);
            acc[0] = fmaf(w, f0.x, acc[0]);
            acc[1] = fmaf(w, f0.y, acc[1]);
            acc[2] = fmaf(w, f1.x, acc[2]);
            acc[3] = fmaf(w, f1.y, acc[3]);
            acc[4] = fmaf(w, f2.x, acc[4]);
            acc[5] = fmaf(w, f2.y, acc[5]);
            acc[6] = fmaf(w, f3.x, acc[6]);
            acc[7] = fmaf(w, f3.y, acc[7]);
            wsum += w;
        }
    }

    float4* dst = (float4*)(out + (long long)warp * DIM) + lane * 2;
    if (e > s) {
        float inv = 1.f / fmaxf(wsum, 1e-12f);
        dst[0] = make_float4(acc[0] * inv, acc[1] * inv, acc[2] * inv, acc[3] * inv);
        dst[1] = make_float4(acc[4] * inv, acc[5] * inv, acc[6] * inv, acc[7] * inv);
    } else {
        float4 z = make_float4(0.f, 0.f, 0.f, 0.f);
        dst[0] = z;
        dst[1] = z;
    }
}

// ---------------------------------------------------------------------------
extern "C" void kernel_launch(void* const* d_in, const int* in_sizes, int n_in,
                              void* d_out, int out_size) {
    const float* x   = (const float*)d_in[0];
    const void*  ei  = d_in[1];
    const float* W1  = (const float*)d_in[2];
    const float* b1  = (const float*)d_in[3];
    const float* W2  = (const float*)d_in[4];
    const float* b2  = (const float*)d_in[5];
    float*       out = (float*)d_out;

    static cudaStream_t s_side = nullptr;
    static cudaEvent_t  ev_fork = nullptr, ev_join = nullptr;
    if (!s_side) {
        cudaStreamCreateWithFlags(&s_side, cudaStreamNonBlocking);
        cudaEventCreateWithFlags(&ev_fork, cudaEventDisableTiming);
        cudaEventCreateWithFlags(&ev_join, cudaEventDisableTiming);
    }

    cudaEventRecord(ev_fork, 0);
    cudaStreamWaitEvent(s_side, ev_fork, 0);

    // side stream: fp16 mirror of x, then CSR build
    const int total4 = N_NODES * (DIM / 4);
    convert_x_kernel<<<(total4 + 255) / 256, 256, 0, s_side>>>((const float4*)x);
    detect_kernel<<<1, 1, 0, s_side>>>((const int*)ei);
    zero_cnt_kernel<<<(N_NODES + 255) / 256, 256, 0, s_side>>>();
    count_kernel<<<(N_EDGES + NTHR - 1) / NTHR, NTHR, 0, s_side>>>(ei);
    scan1_kernel<<<NB_SCAN, SCAN_B, 0, s_side>>>();
    scan2_kernel<<<1, 32, 0, s_side>>>();
    scan3_kernel<<<(N_NODES + 255) / 256, 256, 0, s_side>>>();
    fill_kernel<<<(N_EDGES + NTHR - 1) / NTHR, NTHR, 0, s_side>>>(ei);
    cudaEventRecord(ev_join, s_side);

    // main stream: tiled W1 transpose, then HMMA node weights
    {
        dim3 tb(32, 8);
        dim3 tg(DIM / 32, HID / 32);   // (8, 4)
        prep_w1_kernel<<<tg, tb>>>(W1);
    }
    const int nw_blocks = (N_NODES + TM - 1) / TM;   // 782
    node_weight_kernel<<<nw_blocks, NTHR>>>(x, b1, W2, b2);

    cudaStreamWaitEvent(0, ev_join, 0);
    const int agg_blocks = (N_NODES * 32 + NTHR - 1) / NTHR;  // 6250
    agg_kernel<<<agg_blocks, NTHR>>>(out);
}

// round 12
// speedup vs baseline: 1.1683x; 1.1683x over previous
#include <cuda_runtime.h>
#include <cuda_fp16.h>

#define N_NODES 50000
#define N_EDGES 800000
#define DIM     256
#define HID     128
#define NTHR    256
#define SCAN_B  1024
#define NB_SCAN ((N_NODES + SCAN_B - 1) / SCAN_B)   // 49

#define TM      128                // nodes per block in node_weight
#define LDK     264                // padded fp16 row stride (256 + 8)
#define NW_SMEM (TM * LDK * 2)     // 67584 bytes (dynamic)

__device__ float g_wnode[N_NODES];
__device__ int   g_is64;
__device__ int   g_cnt[N_NODES];
__device__ int   g_incl[N_NODES];
__device__ int   g_btot[64];
__device__ int   g_start[N_NODES + 1];
__device__ int   g_cur[N_NODES + 1];
__device__ int   g_scol[N_EDGES];
__device__ __align__(16) __half g_xh[N_NODES * DIM];   // fp16 mirror of x
__device__ __align__(16) __half g_w1t[HID * DIM];      // W1^T fp16: [n][k]

// ---------------------------------------------------------------------------
__device__ __forceinline__ int load_idx(const void* ei, long long pos, bool is64) {
    int v = is64 ? (int)((const long long*)ei)[pos] : ((const int*)ei)[pos];
    return min(max(v, 0), N_NODES - 1);
}

__device__ __forceinline__ void mma_f16(float* c, const unsigned* a,
                                        unsigned b0, unsigned b1) {
    asm volatile(
        "mma.sync.aligned.m16n8k16.row.col.f32.f16.f16.f32 "
        "{%0,%1,%2,%3}, {%4,%5,%6,%7}, {%8,%9}, {%0,%1,%2,%3};"
        : "+f"(c[0]), "+f"(c[1]), "+f"(c[2]), "+f"(c[3])
        : "r"(a[0]), "r"(a[1]), "r"(a[2]), "r"(a[3]), "r"(b0), "r"(b1));
}

// ---------------------------------------------------------------------------
__global__ void detect_kernel(const int* __restrict__ ei32) {
    int all_hi_zero = 1;
    #pragma unroll 8
    for (int i = 0; i < 512; ++i)
        if (ei32[2 * i + 1] != 0) { all_hi_zero = 0; break; }
    g_is64 = all_hi_zero;
}

__global__ void zero_cnt_kernel() {
    int i = blockIdx.x * blockDim.x + threadIdx.x;
    if (i < N_NODES) g_cnt[i] = 0;
}

// x -> fp16 mirror (for agg gathers)
__global__ void convert_x_kernel(const float4* __restrict__ x4) {
    const int total = N_NODES * (DIM / 4);
    int i = blockIdx.x * blockDim.x + threadIdx.x;
    if (i >= total) return;
    float4 v = __ldg(&x4[i]);
    __half2* dst = (__half2*)g_xh;
    dst[2 * i]     = __floats2half2_rn(v.x, v.y);
    dst[2 * i + 1] = __floats2half2_rn(v.z, v.w);
}

// W1 [k][n] fp32 -> W1^T fp16 [n][k], tiled transpose (coalesced both sides)
__global__ void prep_w1_kernel(const float* __restrict__ W1) {
    __shared__ float t[32][33];
    const int bk = blockIdx.x * 32;
    const int bn = blockIdx.y * 32;
    const int tx = threadIdx.x;
    const int ty = threadIdx.y;
    #pragma unroll
    for (int i = ty; i < 32; i += 8)
        t[i][tx] = __ldg(&W1[(bk + i) * HID + bn + tx]);
    __syncthreads();
    #pragma unroll
    for (int i = ty; i < 32; i += 8)
        g_w1t[(bn + i) * DIM + bk + tx] = __float2half_rn(t[tx][i]);
}

// ---------------------------------------------------------------------------
// CSR build
// ---------------------------------------------------------------------------
__global__ void count_kernel(const void* __restrict__ ei) {
    int e = blockIdx.x * blockDim.x + threadIdx.x;
    if (e >= N_EDGES) return;
    int row = load_idx(ei, e, g_is64 != 0);
    atomicAdd(&g_cnt[row], 1);
}

__global__ void scan1_kernel() {
    __shared__ int s_wt[32];
    const int t = threadIdx.x, b = blockIdx.x;
    const int lane = t & 31, wid = t >> 5;
    const int i = b * SCAN_B + t;
    int sv = (i < N_NODES) ? g_cnt[i] : 0;
    #pragma unroll
    for (int off = 1; off < 32; off <<= 1) {
        int u = __shfl_up_sync(0xffffffffu, sv, off);
        if (lane >= off) sv += u;
    }
    if (lane == 31) s_wt[wid] = sv;
    __syncthreads();
    if (wid == 0) {
        int wv = s_wt[lane];
        #pragma unroll
        for (int off = 1; off < 32; off <<= 1) {
            int u = __shfl_up_sync(0xffffffffu, wv, off);
            if (lane >= off) wv += u;
        }
        s_wt[lane] = wv;
    }
    __syncthreads();
    int incl = sv + ((wid > 0) ? s_wt[wid - 1] : 0);
    if (i < N_NODES) g_incl[i] = incl;
    if (t == SCAN_B - 1) g_btot[b] = incl;
}

__global__ void scan2_kernel() {
    if (threadIdx.x == 0) {
        int run = 0;
        #pragma unroll 1
        for (int b = 0; b < NB_SCAN; ++b) {
            int t = g_btot[b];
            g_btot[b] = run;
            run += t;
        }
    }
}

__global__ void scan3_kernel() {
    int i = blockIdx.x * blockDim.x + threadIdx.x;
    if (i >= N_NODES) return;
    int v = g_incl[i] + g_btot[i >> 10];
    g_start[i + 1] = v;
    g_cur[i + 1]   = v;
    if (i == 0) { g_start[0] = 0; g_cur[0] = 0; }
}

__global__ void fill_kernel(const void* __restrict__ ei) {
    int e = blockIdx.x * blockDim.x + threadIdx.x;
    if (e >= N_EDGES) return;
    bool is64 = (g_is64 != 0);
    int row = load_idx(ei, e, is64);
    int col = load_idx(ei, (long long)N_EDGES + e, is64);
    int pos = atomicAdd(&g_cur[row], 1);
    g_scol[pos] = col;
}

// ---------------------------------------------------------------------------
// Node attention weights: fp16 HMMA, TM=128. Each warp computes TWO M-tiles
// (32 rows) sharing every B fragment -> B LDG per output row HALVED vs R10
// (the node leg was B-LDG-stream bound at ~100 MAC/cyc/SM).
// 8 warps: wm=wid>>1 -> rows [wm*32,+32); wn=wid&1 -> hid cols [wn*64,+64).
// ---------------------------------------------------------------------------
__global__ __launch_bounds__(NTHR)
void node_weight_kernel(const float* __restrict__ x,
                        const float* __restrict__ b1,
                        const float* __restrict__ W2,
                        const float* __restrict__ b2)
{
    extern __shared__ __half sxh[];    // [TM][LDK]
    __shared__ float s_red[2][TM];
    __shared__ float s_b1[HID];
    __shared__ float s_w2[HID];

    const int tid  = threadIdx.x;
    const int lane = tid & 31;
    const int wid  = tid >> 5;
    const int wm   = wid >> 1;        // 0..3 -> rows [wm*32, +32)
    const int wn   = wid & 1;         // 0..1 -> hid cols [wn*64, +64)
    const int base = blockIdx.x * TM;

    if (tid < HID) {
        s_b1[tid] = __ldg(&b1[tid]);
        s_w2[tid] = __ldg(&W2[tid]);
    }

    // --- stage x tile: fp32 -> fp16 in smem (128 rows x 256) ---
    #pragma unroll
    for (int it = 0; it < (TM * (DIM / 4)) / NTHR; ++it) {
        int f = it * NTHR + tid;
        int row = f >> 6;
        int q = f & 63;
        int node = min(base + row, N_NODES - 1);
        float4 v = __ldg(((const float4*)(x + (long long)node * DIM)) + q);
        __half2* o = (__half2*)&sxh[row * LDK + q * 4];
        o[0] = __floats2half2_rn(v.x, v.y);
        o[1] = __floats2half2_rn(v.z, v.w);
    }
    __syncthreads();

    // --- GEMM: 16 k-steps x 8 n-tiles x 2 row-tiles sharing B ---
    float acc[2][8][4];
    #pragma unroll
    for (int t = 0; t < 2; ++t)
        #pragma unroll
        for (int nt = 0; nt < 8; ++nt)
            #pragma unroll
            for (int c = 0; c < 4; ++c) acc[t][nt][c] = 0.f;

    const int r0  = wm * 32 + (lane >> 2);
    const int klo = (lane & 3) * 2;
    const unsigned* W1t32 = (const unsigned*)g_w1t;

    #pragma unroll 1
    for (int ks = 0; ks < DIM / 16; ++ks) {
        const int k = ks * 16 + klo;
        unsigned a0[4], a1[4];
        a0[0] = *(const unsigned*)&sxh[r0 * LDK + k];
        a0[1] = *(const unsigned*)&sxh[(r0 + 8) * LDK + k];
        a0[2] = *(const unsigned*)&sxh[r0 * LDK + k + 8];
        a0[3] = *(const unsigned*)&sxh[(r0 + 8) * LDK + k + 8];
        a1[0] = *(const unsigned*)&sxh[(r0 + 16) * LDK + k];
        a1[1] = *(const unsigned*)&sxh[(r0 + 24) * LDK + k];
        a1[2] = *(const unsigned*)&sxh[(r0 + 16) * LDK + k + 8];
        a1[3] = *(const unsigned*)&sxh[(r0 + 24) * LDK + k + 8];

        #pragma unroll
        for (int nt = 0; nt < 8; ++nt) {
            const int n0 = wn * 64 + nt * 8 + (lane >> 2);
            const int bo = (n0 * DIM + ks * 16 + klo) >> 1;
            unsigned b0 = __ldg(&W1t32[bo]);
            unsigned b1r = __ldg(&W1t32[bo + 4]);
            mma_f16(acc[0][nt], a0, b0, b1r);   // B reused across both
            mma_f16(acc[1][nt], a1, b0, b1r);   // row tiles
        }
    }

    // --- epilogue per row tile: relu(+b1).W2, lane-pair reduce, store ---
    #pragma unroll
    for (int t = 0; t < 2; ++t) {
        float sA = 0.f, sB = 0.f;
        #pragma unroll
        for (int nt = 0; nt < 8; ++nt) {
            int j0 = wn * 64 + nt * 8 + (lane & 3) * 2;
            float bb0 = s_b1[j0],  bb1 = s_b1[j0 + 1];
            float ww0 = s_w2[j0],  ww1 = s_w2[j0 + 1];
            sA = fmaf(fmaxf(acc[t][nt][0] + bb0, 0.f), ww0, sA);
            sA = fmaf(fmaxf(acc[t][nt][1] + bb1, 0.f), ww1, sA);
            sB = fmaf(fmaxf(acc[t][nt][2] + bb0, 0.f), ww0, sB);
            sB = fmaf(fmaxf(acc[t][nt][3] + bb1, 0.f), ww1, sB);
        }
        sA += __shfl_xor_sync(0xffffffffu, sA, 1);
        sA += __shfl_xor_sync(0xffffffffu, sA, 2);
        sB += __shfl_xor_sync(0xffffffffu, sB, 1);
        sB += __shfl_xor_sync(0xffffffffu, sB, 2);
        if ((lane & 3) == 0) {
            int r = wm * 32 + t * 16 + (lane >> 2);
            s_red[wn][r]     = sA;
            s_red[wn][r + 8] = sB;
        }
    }
    __syncthreads();

    if (tid < TM) {
        int node = base + tid;
        if (node < N_NODES) {
            float logit = s_red[0][tid] + s_red[1][tid] + __ldg(b2);
            g_wnode[node] = 1.f / (1.f + expf(-logit));
        }
    }
}

// ---------------------------------------------------------------------------
// Aggregation: R10 form exactly (the R11 prefetch pipeline regressed).
// ---------------------------------------------------------------------------
__global__ __launch_bounds__(NTHR, 8)
void agg_kernel(float* __restrict__ out)
{
    const int warp = (blockIdx.x * NTHR + threadIdx.x) >> 5;
    const int lane = threadIdx.x & 31;
    if (warp >= N_NODES) return;

    const int s = g_start[warp];
    const int e = g_start[warp + 1];

    float acc[8] = {0.f, 0.f, 0.f, 0.f, 0.f, 0.f, 0.f, 0.f};
    float wsum = 0.f;

    for (int base = s; base < e; base += 32) {
        const int n = min(32, e - base);
        int   col = 0;
        float wv  = 0.f;
        if (lane < n) {
            col = g_scol[base + lane];
            wv  = __ldg(&g_wnode[col]);
        }
        for (int c = 0; c < n; ++c) {
            int   cc = __shfl_sync(0xffffffffu, col, c);
            float ww = __shfl_sync(0xffffffffu, wv,  c);
            const uint4* src = (const uint4*)(g_xh + (long long)cc * DIM);
            uint4 p = __ldg(src + lane);
            float2 f0 = __half22float2(*(const __half2*)&p.x);
            float2 f1 = __half22float2(*(const __half2*)&p.y);
            float2 f2 = __half22float2(*(const __half2*)&p.z);
            float2 f3 = __half22float2(*(const __half2*)&p.w);
            acc[0] = fmaf(ww, f0.x, acc[0]);
            acc[1] = fmaf(ww, f0.y, acc[1]);
            acc[2] = fmaf(ww, f1.x, acc[2]);
            acc[3] = fmaf(ww, f1.y, acc[3]);
            acc[4] = fmaf(ww, f2.x, acc[4]);
            acc[5] = fmaf(ww, f2.y, acc[5]);
            acc[6] = fmaf(ww, f3.x, acc[6]);
            acc[7] = fmaf(ww, f3.y, acc[7]);
            wsum += ww;
        }
    }

    float4* dst = (float4*)(out + (long long)warp * DIM) + lane * 2;
    if (e > s) {
        float inv = 1.f / fmaxf(wsum, 1e-12f);
        dst[0] = make_float4(acc[0] * inv, acc[1] * inv, acc[2] * inv, acc[3] * inv);
        dst[1] = make_float4(acc[4] * inv, acc[5] * inv, acc[6] * inv, acc[7] * inv);
    } else {
        float4 z = make_float4(0.f, 0.f, 0.f, 0.f);
        dst[0] = z;
        dst[1] = z;
    }
}

// ---------------------------------------------------------------------------
extern "C" void kernel_launch(void* const* d_in, const int* in_sizes, int n_in,
                              void* d_out, int out_size) {
    const float* x   = (const float*)d_in[0];
    const void*  ei  = d_in[1];
    const float* W1  = (const float*)d_in[2];
    const float* b1  = (const float*)d_in[3];
    const float* W2  = (const float*)d_in[4];
    const float* b2  = (const float*)d_in[5];
    float*       out = (float*)d_out;

    static cudaStream_t s_side = nullptr;
    static cudaEvent_t  ev_fork = nullptr, ev_join = nullptr;
    if (!s_side) {
        cudaStreamCreateWithFlags(&s_side, cudaStreamNonBlocking);
        cudaEventCreateWithFlags(&ev_fork, cudaEventDisableTiming);
        cudaEventCreateWithFlags(&ev_join, cudaEventDisableTiming);
        cudaFuncSetAttribute(node_weight_kernel,
                             cudaFuncAttributeMaxDynamicSharedMemorySize, NW_SMEM);
    }

    cudaEventRecord(ev_fork, 0);
    cudaStreamWaitEvent(s_side, ev_fork, 0);

    // side stream: fp16 mirror of x, then CSR build
    const int total4 = N_NODES * (DIM / 4);
    convert_x_kernel<<<(total4 + 255) / 256, 256, 0, s_side>>>((const float4*)x);
    detect_kernel<<<1, 1, 0, s_side>>>((const int*)ei);
    zero_cnt_kernel<<<(N_NODES + 255) / 256, 256, 0, s_side>>>();
    count_kernel<<<(N_EDGES + NTHR - 1) / NTHR, NTHR, 0, s_side>>>(ei);
    scan1_kernel<<<NB_SCAN, SCAN_B, 0, s_side>>>();
    scan2_kernel<<<1, 32, 0, s_side>>>();
    scan3_kernel<<<(N_NODES + 255) / 256, 256, 0, s_side>>>();
    fill_kernel<<<(N_EDGES + NTHR - 1) / NTHR, NTHR, 0, s_side>>>(ei);
    cudaEventRecord(ev_join, s_side);

    // main stream: tiled W1 transpose, then HMMA node weights (TM=128)
    {
        dim3 tb(32, 8);
        dim3 tg(DIM / 32, HID / 32);   // (8, 4)
        prep_w1_kernel<<<tg, tb>>>(W1);
    }
    const int nw_blocks = (N_NODES + TM - 1) / TM;   // 391
    node_weight_kernel<<<nw_blocks, NTHR, NW_SMEM>>>(x, b1, W2, b2);

    cudaStreamWaitEvent(0, ev_join, 0);
    const int agg_blocks = (N_NODES * 32 + NTHR - 1) / NTHR;  // 6250
    agg_kernel<<<agg_blocks, NTHR>>>(out);
}

// round 13
// speedup vs baseline: 1.3318x; 1.1399x over previous
#include <cuda_runtime.h>
#include <cuda_fp16.h>

#define N_NODES 50000
#define N_EDGES 800000
#define DIM     256
#define HID     128
#define NTHR    256
#define SCAN_B  1024
#define NB_SCAN ((N_NODES + SCAN_B - 1) / SCAN_B)   // 49

#define TM      128                // nodes per block in node_weight
#define LDK     264                // padded fp16 row stride (256 + 8)
#define NW_SMEM (TM * LDK * 2)     // 67584 bytes (dynamic)

__device__ float g_wnode[N_NODES];
__device__ int   g_is64;
__device__ int   g_cnt[N_NODES];
__device__ int   g_incl[N_NODES];
__device__ int   g_btot[64];
__device__ int   g_start[N_NODES + 1];
__device__ int   g_cur[N_NODES + 1];
__device__ int   g_scol[N_EDGES];
__device__ __align__(16) __half g_xh[N_NODES * DIM];      // fp16 mirror of x
__device__ __align__(16) unsigned g_w1p[HID * (DIM / 2)]; // packed B fragments (64KB)

// ---------------------------------------------------------------------------
__device__ __forceinline__ int load_idx(const void* ei, long long pos, bool is64) {
    int v = is64 ? (int)((const long long*)ei)[pos] : ((const int*)ei)[pos];
    return min(max(v, 0), N_NODES - 1);
}

__device__ __forceinline__ void mma_f16(float* c, const unsigned* a,
                                        unsigned b0, unsigned b1) {
    asm volatile(
        "mma.sync.aligned.m16n8k16.row.col.f32.f16.f16.f32 "
        "{%0,%1,%2,%3}, {%4,%5,%6,%7}, {%8,%9}, {%0,%1,%2,%3};"
        : "+f"(c[0]), "+f"(c[1]), "+f"(c[2]), "+f"(c[3])
        : "r"(a[0]), "r"(a[1]), "r"(a[2]), "r"(a[3]), "r"(b0), "r"(b1));
}

// ---------------------------------------------------------------------------
__global__ void detect_kernel(const int* __restrict__ ei32) {
    int all_hi_zero = 1;
    #pragma unroll 8
    for (int i = 0; i < 512; ++i)
        if (ei32[2 * i + 1] != 0) { all_hi_zero = 0; break; }
    g_is64 = all_hi_zero;
}

__global__ void zero_cnt_kernel() {
    int i = blockIdx.x * blockDim.x + threadIdx.x;
    if (i < N_NODES) g_cnt[i] = 0;
}

// x -> fp16 mirror (for agg gathers)
__global__ void convert_x_kernel(const float4* __restrict__ x4) {
    const int total = N_NODES * (DIM / 4);
    int i = blockIdx.x * blockDim.x + threadIdx.x;
    if (i >= total) return;
    float4 v = __ldg(&x4[i]);
    __half2* dst = (__half2*)g_xh;
    dst[2 * i]     = __floats2half2_rn(v.x, v.y);
    dst[2 * i + 1] = __floats2half2_rn(v.z, v.w);
}

// W1 [k][n] fp32 -> packed fp16 B-fragment table.
// Fragment u32 for (n, ku): halfs (W1[2ku][n], W1[2ku+1][n]).
// Decompose ku: ks=ku>>3, rem=ku&7, f=rem>>2, q=rem&3; ir=ks*2+f;
// chunk=ir>>2, j=ir&3, lane=(n&7)*4+q, ntf=n>>3.
// pidx = (((ntf*8 + chunk)*32) + lane)*4 + j  -> one LDG.128 per lane per
// (ntf, chunk) delivers frags for 2 consecutive k-steps, warp-coalesced.
__global__ void prep_w1_pack_kernel(const float* __restrict__ W1) {
    int i = blockIdx.x * blockDim.x + threadIdx.x;   // over HID * DIM/2
    if (i >= HID * (DIM / 2)) return;
    int ku = i >> 7;          // 0..127  (u32 index within row)
    int n  = i & (HID - 1);   // 0..127  (consecutive threads -> coalesced read)
    float f0 = __ldg(&W1[(2 * ku) * HID + n]);
    float f1 = __ldg(&W1[(2 * ku + 1) * HID + n]);
    __half2 h = __floats2half2_rn(f0, f1);
    int ks = ku >> 3, rem = ku & 7;
    int f = rem >> 2, q = rem & 3;
    int ir = ks * 2 + f;
    int chunk = ir >> 2, j = ir & 3;
    int lane = (n & 7) * 4 + q;
    int ntf = n >> 3;
    int pidx = (((ntf * 8 + chunk) * 32) + lane) * 4 + j;
    g_w1p[pidx] = *(unsigned*)&h;
}

// ---------------------------------------------------------------------------
// CSR build
// ---------------------------------------------------------------------------
__global__ void count_kernel(const void* __restrict__ ei) {
    int e = blockIdx.x * blockDim.x + threadIdx.x;
    if (e >= N_EDGES) return;
    int row = load_idx(ei, e, g_is64 != 0);
    atomicAdd(&g_cnt[row], 1);
}

__global__ void scan1_kernel() {
    __shared__ int s_wt[32];
    const int t = threadIdx.x, b = blockIdx.x;
    const int lane = t & 31, wid = t >> 5;
    const int i = b * SCAN_B + t;
    int sv = (i < N_NODES) ? g_cnt[i] : 0;
    #pragma unroll
    for (int off = 1; off < 32; off <<= 1) {
        int u = __shfl_up_sync(0xffffffffu, sv, off);
        if (lane >= off) sv += u;
    }
    if (lane == 31) s_wt[wid] = sv;
    __syncthreads();
    if (wid == 0) {
        int wv = s_wt[lane];
        #pragma unroll
        for (int off = 1; off < 32; off <<= 1) {
            int u = __shfl_up_sync(0xffffffffu, wv, off);
            if (lane >= off) wv += u;
        }
        s_wt[lane] = wv;
    }
    __syncthreads();
    int incl = sv + ((wid > 0) ? s_wt[wid - 1] : 0);
    if (i < N_NODES) g_incl[i] = incl;
    if (t == SCAN_B - 1) g_btot[b] = incl;
}

__global__ void scan2_kernel() {
    if (threadIdx.x == 0) {
        int run = 0;
        #pragma unroll 1
        for (int b = 0; b < NB_SCAN; ++b) {
            int t = g_btot[b];
            g_btot[b] = run;
            run += t;
        }
    }
}

__global__ void scan3_kernel() {
    int i = blockIdx.x * blockDim.x + threadIdx.x;
    if (i >= N_NODES) return;
    int v = g_incl[i] + g_btot[i >> 10];
    g_start[i + 1] = v;
    g_cur[i + 1]   = v;
    if (i == 0) { g_start[0] = 0; g_cur[0] = 0; }
}

__global__ void fill_kernel(const void* __restrict__ ei) {
    int e = blockIdx.x * blockDim.x + threadIdx.x;
    if (e >= N_EDGES) return;
    bool is64 = (g_is64 != 0);
    int row = load_idx(ei, e, is64);
    int col = load_idx(ei, (long long)N_EDGES + e, is64);
    int pos = atomicAdd(&g_cur[row], 1);
    g_scol[pos] = col;
}

// ---------------------------------------------------------------------------
// Node attention weights: fp16 HMMA, TM=128, 2 row-tiles per warp sharing B,
// and B via packed LDG.128 (4 fragments per load -> 4x fewer B load slots).
// ---------------------------------------------------------------------------
__global__ __launch_bounds__(NTHR)
void node_weight_kernel(const float* __restrict__ x,
                        const float* __restrict__ b1,
                        const float* __restrict__ W2,
                        const float* __restrict__ b2)
{
    extern __shared__ __half sxh[];    // [TM][LDK]
    __shared__ float s_red[2][TM];
    __shared__ float s_b1[HID];
    __shared__ float s_w2[HID];

    const int tid  = threadIdx.x;
    const int lane = tid & 31;
    const int wid  = tid >> 5;
    const int wm   = wid >> 1;        // 0..3 -> rows [wm*32, +32)
    const int wn   = wid & 1;         // 0..1 -> hid cols [wn*64, +64)
    const int base = blockIdx.x * TM;

    if (tid < HID) {
        s_b1[tid] = __ldg(&b1[tid]);
        s_w2[tid] = __ldg(&W2[tid]);
    }

    // --- stage x tile: fp32 -> fp16 in smem (128 rows x 256) ---
    #pragma unroll
    for (int it = 0; it < (TM * (DIM / 4)) / NTHR; ++it) {
        int f = it * NTHR + tid;
        int row = f >> 6;
        int q = f & 63;
        int node = min(base + row, N_NODES - 1);
        float4 v = __ldg(((const float4*)(x + (long long)node * DIM)) + q);
        __half2* o = (__half2*)&sxh[row * LDK + q * 4];
        o[0] = __floats2half2_rn(v.x, v.y);
        o[1] = __floats2half2_rn(v.z, v.w);
    }
    __syncthreads();

    // --- GEMM: 8 chunks (2 k-steps each) x 8 n-tiles x 2 row-tiles ---
    float acc[2][8][4];
    #pragma unroll
    for (int t = 0; t < 2; ++t)
        #pragma unroll
        for (int nt = 0; nt < 8; ++nt)
            #pragma unroll
            for (int c = 0; c < 4; ++c) acc[t][nt][c] = 0.f;

    const int r0  = wm * 32 + (lane >> 2);
    const int klo = (lane & 3) * 2;
    const uint4* Bp = (const uint4*)g_w1p;   // [(ntf*8+chunk)*32 + lane]

    #pragma unroll 1
    for (int chunk = 0; chunk < 8; ++chunk) {
        unsigned aA[2][4], aB[2][4];   // [ks-in-chunk][frag], row tiles A/B
        #pragma unroll
        for (int t = 0; t < 2; ++t) {
            const int k = (chunk * 2 + t) * 16 + klo;
            aA[t][0] = *(const unsigned*)&sxh[r0 * LDK + k];
            aA[t][1] = *(const unsigned*)&sxh[(r0 + 8) * LDK + k];
            aA[t][2] = *(const unsigned*)&sxh[r0 * LDK + k + 8];
            aA[t][3] = *(const unsigned*)&sxh[(r0 + 8) * LDK + k + 8];
            aB[t][0] = *(const unsigned*)&sxh[(r0 + 16) * LDK + k];
            aB[t][1] = *(const unsigned*)&sxh[(r0 + 24) * LDK + k];
            aB[t][2] = *(const unsigned*)&sxh[(r0 + 16) * LDK + k + 8];
            aB[t][3] = *(const unsigned*)&sxh[(r0 + 24) * LDK + k + 8];
        }
        #pragma unroll
        for (int nt = 0; nt < 8; ++nt) {
            const int ntf = wn * 8 + nt;
            uint4 b = __ldg(&Bp[(ntf * 8 + chunk) * 32 + lane]);
            mma_f16(acc[0][nt], aA[0], b.x, b.y);   // ks0, both row tiles
            mma_f16(acc[1][nt], aB[0], b.x, b.y);
            mma_f16(acc[0][nt], aA[1], b.z, b.w);   // ks1
            mma_f16(acc[1][nt], aB[1], b.z, b.w);
        }
    }

    // --- epilogue per row tile: relu(+b1).W2, lane-pair reduce, store ---
    #pragma unroll
    for (int t = 0; t < 2; ++t) {
        float sA = 0.f, sB = 0.f;
        #pragma unroll
        for (int nt = 0; nt < 8; ++nt) {
            int j0 = wn * 64 + nt * 8 + (lane & 3) * 2;
            float bb0 = s_b1[j0],  bb1 = s_b1[j0 + 1];
            float ww0 = s_w2[j0],  ww1 = s_w2[j0 + 1];
            sA = fmaf(fmaxf(acc[t][nt][0] + bb0, 0.f), ww0, sA);
            sA = fmaf(fmaxf(acc[t][nt][1] + bb1, 0.f), ww1, sA);
            sB = fmaf(fmaxf(acc[t][nt][2] + bb0, 0.f), ww0, sB);
            sB = fmaf(fmaxf(acc[t][nt][3] + bb1, 0.f), ww1, sB);
        }
        sA += __shfl_xor_sync(0xffffffffu, sA, 1);
        sA += __shfl_xor_sync(0xffffffffu, sA, 2);
        sB += __shfl_xor_sync(0xffffffffu, sB, 1);
        sB += __shfl_xor_sync(0xffffffffu, sB, 2);
        if ((lane & 3) == 0) {
            int r = wm * 32 + t * 16 + (lane >> 2);
            s_red[wn][r]     = sA;
            s_red[wn][r + 8] = sB;
        }
    }
    __syncthreads();

    if (tid < TM) {
        int node = base + tid;
        if (node < N_NODES) {
            float logit = s_red[0][tid] + s_red[1][tid] + __ldg(b2);
            g_wnode[node] = 1.f / (1.f + expf(-logit));
        }
    }
}

// ---------------------------------------------------------------------------
// Aggregation: R10 form (prefetch variant regressed in R11).
// ---------------------------------------------------------------------------
__global__ __launch_bounds__(NTHR, 8)
void agg_kernel(float* __restrict__ out)
{
    const int warp = (blockIdx.x * NTHR + threadIdx.x) >> 5;
    const int lane = threadIdx.x & 31;
    if (warp >= N_NODES) return;

    const int s = g_start[warp];
    const int e = g_start[warp + 1];

    float acc[8] = {0.f, 0.f, 0.f, 0.f, 0.f, 0.f, 0.f, 0.f};
    float wsum = 0.f;

    for (int base = s; base < e; base += 32) {
        const int n = min(32, e - base);
        int   col = 0;
        float wv  = 0.f;
        if (lane < n) {
            col = g_scol[base + lane];
            wv  = __ldg(&g_wnode[col]);
        }
        for (int c = 0; c < n; ++c) {
            int   cc = __shfl_sync(0xffffffffu, col, c);
            float ww = __shfl_sync(0xffffffffu, wv,  c);
            const uint4* src = (const uint4*)(g_xh + (long long)cc * DIM);
            uint4 p = __ldg(src + lane);
            float2 f0 = __half22float2(*(const __half2*)&p.x);
            float2 f1 = __half22float2(*(const __half2*)&p.y);
            float2 f2 = __half22float2(*(const __half2*)&p.z);
            float2 f3 = __half22float2(*(const __half2*)&p.w);
            acc[0] = fmaf(ww, f0.x, acc[0]);
            acc[1] = fmaf(ww, f0.y, acc[1]);
            acc[2] = fmaf(ww, f1.x, acc[2]);
            acc[3] = fmaf(ww, f1.y, acc[3]);
            acc[4] = fmaf(ww, f2.x, acc[4]);
            acc[5] = fmaf(ww, f2.y, acc[5]);
            acc[6] = fmaf(ww, f3.x, acc[6]);
            acc[7] = fmaf(ww, f3.y, acc[7]);
            wsum += ww;
        }
    }

    float4* dst = (float4*)(out + (long long)warp * DIM) + lane * 2;
    if (e > s) {
        float inv = 1.f / fmaxf(wsum, 1e-12f);
        dst[0] = make_float4(acc[0] * inv, acc[1] * inv, acc[2] * inv, acc[3] * inv);
        dst[1] = make_float4(acc[4] * inv, acc[5] * inv, acc[6] * inv, acc[7] * inv);
    } else {
        float4 z = make_float4(0.f, 0.f, 0.f, 0.f);
        dst[0] = z;
        dst[1] = z;
    }
}

// ---------------------------------------------------------------------------
extern "C" void kernel_launch(void* const* d_in, const int* in_sizes, int n_in,
                              void* d_out, int out_size) {
    const float* x   = (const float*)d_in[0];
    const void*  ei  = d_in[1];
    const float* W1  = (const float*)d_in[2];
    const float* b1  = (const float*)d_in[3];
    const float* W2  = (const float*)d_in[4];
    const float* b2  = (const float*)d_in[5];
    float*       out = (float*)d_out;

    static cudaStream_t s_side = nullptr;
    static cudaEvent_t  ev_fork = nullptr, ev_join = nullptr;
    if (!s_side) {
        cudaStreamCreateWithFlags(&s_side, cudaStreamNonBlocking);
        cudaEventCreateWithFlags(&ev_fork, cudaEventDisableTiming);
        cudaEventCreateWithFlags(&ev_join, cudaEventDisableTiming);
        cudaFuncSetAttribute(node_weight_kernel,
                             cudaFuncAttributeMaxDynamicSharedMemorySize, NW_SMEM);
    }

    cudaEventRecord(ev_fork, 0);
    cudaStreamWaitEvent(s_side, ev_fork, 0);

    // side stream: fp16 mirror of x, then CSR build
    const int total4 = N_NODES * (DIM / 4);
    convert_x_kernel<<<(total4 + 255) / 256, 256, 0, s_side>>>((const float4*)x);
    detect_kernel<<<1, 1, 0, s_side>>>((const int*)ei);
    zero_cnt_kernel<<<(N_NODES + 255) / 256, 256, 0, s_side>>>();
    count_kernel<<<(N_EDGES + NTHR - 1) / NTHR, NTHR, 0, s_side>>>(ei);
    scan1_kernel<<<NB_SCAN, SCAN_B, 0, s_side>>>();
    scan2_kernel<<<1, 32, 0, s_side>>>();
    scan3_kernel<<<(N_NODES + 255) / 256, 256, 0, s_side>>>();
    fill_kernel<<<(N_EDGES + NTHR - 1) / NTHR, NTHR, 0, s_side>>>(ei);
    cudaEventRecord(ev_join, s_side);

    // main stream: B-fragment pack, then HMMA node weights (TM=128)
    prep_w1_pack_kernel<<<(HID * (DIM / 2) + 255) / 256, 256>>>(W1);
    const int nw_blocks = (N_NODES + TM - 1) / TM;   // 391
    node_weight_kernel<<<nw_blocks, NTHR, NW_SMEM>>>(x, b1, W2, b2);

    cudaStreamWaitEvent(0, ev_join, 0);
    const int agg_blocks = (N_NODES * 32 + NTHR - 1) / NTHR;  // 6250
    agg_kernel<<<agg_blocks, NTHR>>>(out);
}

// round 15
// speedup vs baseline: 1.4396x; 1.0809x over previous
#include <cuda_runtime.h>
#include <cuda_fp16.h>
#include <cstdint>

#define N_NODES 50000
#define N_EDGES 800000
#define DIM     256
#define HID     128
#define NTHR    256
#define SCAN_B  1024
#define NB_SCAN ((N_NODES + SCAN_B - 1) / SCAN_B)   // 49

#define TM      128                // nodes per block in node_weight
#define LDK     264                // padded fp16 row stride (256 + 8)
#define NW_SMEM (TM * LDK * 2)     // 67584 bytes (dynamic)

__device__ float g_wnode[N_NODES];
__device__ int   g_is64;
__device__ int   g_cnt[N_NODES];
__device__ int   g_incl[N_NODES];
__device__ int   g_btot[64];
__device__ int   g_start[N_NODES + 1];
__device__ int   g_cur[N_NODES + 1];
__device__ int   g_scol[N_EDGES];
__device__ __align__(16) __half g_xh[N_NODES * DIM];      // fp16 mirror of x
__device__ __align__(16) unsigned g_w1p[HID * (DIM / 2)]; // packed B fragments (64KB)

// ---------------------------------------------------------------------------
__device__ __forceinline__ int load_idx(const void* ei, long long pos, bool is64) {
    int v = is64 ? (int)((const long long*)ei)[pos] : ((const int*)ei)[pos];
    return min(max(v, 0), N_NODES - 1);
}

__device__ __forceinline__ void mma_f16(float* c, const unsigned* a,
                                        unsigned b0, unsigned b1) {
    asm volatile(
        "mma.sync.aligned.m16n8k16.row.col.f32.f16.f16.f32 "
        "{%0,%1,%2,%3}, {%4,%5,%6,%7}, {%8,%9}, {%0,%1,%2,%3};"
        : "+f"(c[0]), "+f"(c[1]), "+f"(c[2]), "+f"(c[3])
        : "r"(a[0]), "r"(a[1]), "r"(a[2]), "r"(a[3]), "r"(b0), "r"(b1));
}

#define LDSM_X4(r0, r1, r2, r3, addr)                                          \
    asm volatile("ldmatrix.sync.aligned.m8n8.x4.shared.b16 {%0,%1,%2,%3}, [%4];" \
                 : "=r"(r0), "=r"(r1), "=r"(r2), "=r"(r3) : "r"(addr))

// ---------------------------------------------------------------------------
__global__ void detect_kernel(const int* __restrict__ ei32) {
    int all_hi_zero = 1;
    #pragma unroll 8
    for (int i = 0; i < 512; ++i)
        if (ei32[2 * i + 1] != 0) { all_hi_zero = 0; break; }
    g_is64 = all_hi_zero;
}

__global__ void zero_cnt_kernel() {
    int i = blockIdx.x * blockDim.x + threadIdx.x;
    if (i < N_NODES) g_cnt[i] = 0;
}

// x -> fp16 mirror (for agg gathers)
__global__ void convert_x_kernel(const float4* __restrict__ x4) {
    const int total = N_NODES * (DIM / 4);
    int i = blockIdx.x * blockDim.x + threadIdx.x;
    if (i >= total) return;
    float4 v = __ldg(&x4[i]);
    __half2* dst = (__half2*)g_xh;
    dst[2 * i]     = __floats2half2_rn(v.x, v.y);
    dst[2 * i + 1] = __floats2half2_rn(v.z, v.w);
}

// W1 [k][n] fp32 -> packed fp16 B-fragment table (same layout as R13).
__global__ void prep_w1_pack_kernel(const float* __restrict__ W1) {
    int i = blockIdx.x * blockDim.x + threadIdx.x;   // over HID * DIM/2
    if (i >= HID * (DIM / 2)) return;
    int ku = i >> 7;
    int n  = i & (HID - 1);
    float f0 = __ldg(&W1[(2 * ku) * HID + n]);
    float f1 = __ldg(&W1[(2 * ku + 1) * HID + n]);
    __half2 h = __floats2half2_rn(f0, f1);
    int ks = ku >> 3, rem = ku & 7;
    int f = rem >> 2, q = rem & 3;
    int ir = ks * 2 + f;
    int chunk = ir >> 2, j = ir & 3;
    int lane = (n & 7) * 4 + q;
    int ntf = n >> 3;
    int pidx = (((ntf * 8 + chunk) * 32) + lane) * 4 + j;
    g_w1p[pidx] = *(unsigned*)&h;
}

// ---------------------------------------------------------------------------
// CSR build
// ---------------------------------------------------------------------------
__global__ void count_kernel(const void* __restrict__ ei) {
    int e = blockIdx.x * blockDim.x + threadIdx.x;
    if (e >= N_EDGES) return;
    int row = load_idx(ei, e, g_is64 != 0);
    atomicAdd(&g_cnt[row], 1);
}

__global__ void scan1_kernel() {
    __shared__ int s_wt[32];
    const int t = threadIdx.x, b = blockIdx.x;
    const int lane = t & 31, wid = t >> 5;
    const int i = b * SCAN_B + t;
    int sv = (i < N_NODES) ? g_cnt[i] : 0;
    #pragma unroll
    for (int off = 1; off < 32; off <<= 1) {
        int u = __shfl_up_sync(0xffffffffu, sv, off);
        if (lane >= off) sv += u;
    }
    if (lane == 31) s_wt[wid] = sv;
    __syncthreads();
    if (wid == 0) {
        int wv = s_wt[lane];
        #pragma unroll
        for (int off = 1; off < 32; off <<= 1) {
            int u = __shfl_up_sync(0xffffffffu, wv, off);
            if (lane >= off) wv += u;
        }
        s_wt[lane] = wv;
    }
    __syncthreads();
    int incl = sv + ((wid > 0) ? s_wt[wid - 1] : 0);
    if (i < N_NODES) g_incl[i] = incl;
    if (t == SCAN_B - 1) g_btot[b] = incl;
}

__global__ void scan2_kernel() {
    if (threadIdx.x == 0) {
        int run = 0;
        #pragma unroll 1
        for (int b = 0; b < NB_SCAN; ++b) {
            int t = g_btot[b];
            g_btot[b] = run;
            run += t;
        }
    }
}

__global__ void scan3_kernel() {
    int i = blockIdx.x * blockDim.x + threadIdx.x;
    if (i >= N_NODES) return;
    int v = g_incl[i] + g_btot[i >> 10];
    g_start[i + 1] = v;
    g_cur[i + 1]   = v;
    if (i == 0) { g_start[0] = 0; g_cur[0] = 0; }
}

__global__ void fill_kernel(const void* __restrict__ ei) {
    int e = blockIdx.x * blockDim.x + threadIdx.x;
    if (e >= N_EDGES) return;
    bool is64 = (g_is64 != 0);
    int row = load_idx(ei, e, is64);
    int col = load_idx(ei, (long long)N_EDGES + e, is64);
    int pos = atomicAdd(&g_cur[row], 1);
    g_scol[pos] = col;
}

// ---------------------------------------------------------------------------
// Node attention weights: fp16 HMMA, TM=128. Each warp owns 16 n-cols
// (2 n-tiles) x ALL 128 rows -> every B fragment loaded ONCE per warp,
// reused across 8 row-tiles. B LDG.128/block: 512 -> 128. A fragments via
// ldmatrix.x4 (row = rt*16+(lane&15), k-half = lane>=16).
// ---------------------------------------------------------------------------
__global__ __launch_bounds__(NTHR)
void node_weight_kernel(const float* __restrict__ x,
                        const float* __restrict__ b1,
                        const float* __restrict__ W2,
                        const float* __restrict__ b2)
{
    extern __shared__ __half sxh[];    // [TM][LDK]
    __shared__ float s_red[8][TM];     // per-warp 16-col partials
    __shared__ float s_b1[HID];
    __shared__ float s_w2[HID];

    const int tid  = threadIdx.x;
    const int lane = tid & 31;
    const int w    = tid >> 5;        // warp 0..7 -> n cols [w*16, +16)
    const int base = blockIdx.x * TM;

    if (tid < HID) {
        s_b1[tid] = __ldg(&b1[tid]);
        s_w2[tid] = __ldg(&W2[tid]);
    }

    // --- stage x tile: fp32 -> fp16 in smem (128 rows x 256) ---
    #pragma unroll
    for (int it = 0; it < (TM * (DIM / 4)) / NTHR; ++it) {
        int f = it * NTHR + tid;
        int row = f >> 6;
        int q = f & 63;
        int node = min(base + row, N_NODES - 1);
        float4 v = __ldg(((const float4*)(x + (long long)node * DIM)) + q);
        __half2* o = (__half2*)&sxh[row * LDK + q * 4];
        o[0] = __floats2half2_rn(v.x, v.y);
        o[1] = __floats2half2_rn(v.z, v.w);
    }
    __syncthreads();

    // --- GEMM: 8 chunks x 8 row-tiles x 2 n-tiles, B loaded once per chunk ---
    float acc[8][2][4];
    #pragma unroll
    for (int rt = 0; rt < 8; ++rt)
        #pragma unroll
        for (int nt = 0; nt < 2; ++nt)
            #pragma unroll
            for (int c = 0; c < 4; ++c) acc[rt][nt][c] = 0.f;

    const uint4* Bp = (const uint4*)g_w1p;
    const unsigned sbase = (unsigned)__cvta_generic_to_shared(sxh);
    // lane's ldmatrix row address: row = (lane&15), k-half byte offset = (lane>>4)*16
    const unsigned a_lane = sbase + ((unsigned)(lane & 15) * LDK) * 2u
                          + (unsigned)(lane >> 4) * 16u;

    #pragma unroll 1
    for (int chunk = 0; chunk < 8; ++chunk) {
        uint4 b0  = __ldg(&Bp[((2 * w)     * 8 + chunk) * 32 + lane]);
        uint4 b1f = __ldg(&Bp[((2 * w + 1) * 8 + chunk) * 32 + lane]);
        const unsigned kb = (unsigned)chunk * 64u;   // chunk*32 halfs = 64 bytes
        #pragma unroll
        for (int rt = 0; rt < 8; ++rt) {
            unsigned ad = a_lane + (unsigned)(rt * 16 * LDK) * 2u + kb;
            unsigned aK0[4], aK1[4];
            LDSM_X4(aK0[0], aK0[1], aK0[2], aK0[3], ad);        // k 0..15 of chunk
            LDSM_X4(aK1[0], aK1[1], aK1[2], aK1[3], ad + 32u);  // k 16..31
            mma_f16(acc[rt][0], aK0, b0.x,  b0.y);
            mma_f16(acc[rt][1], aK0, b1f.x, b1f.y);
            mma_f16(acc[rt][0], aK1, b0.z,  b0.w);
            mma_f16(acc[rt][1], aK1, b1f.z, b1f.w);
        }
    }

    // --- epilogue: relu(+b1).W2 over this warp's 16 cols, per row ---
    #pragma unroll
    for (int rt = 0; rt < 8; ++rt) {
        float sA = 0.f, sB = 0.f;
        #pragma unroll
        for (int nt = 0; nt < 2; ++nt) {
            int j0 = w * 16 + nt * 8 + (lane & 3) * 2;
            float bb0 = s_b1[j0],  bb1 = s_b1[j0 + 1];
            float ww0 = s_w2[j0],  ww1 = s_w2[j0 + 1];
            sA = fmaf(fmaxf(acc[rt][nt][0] + bb0, 0.f), ww0, sA);
            sA = fmaf(fmaxf(acc[rt][nt][1] + bb1, 0.f), ww1, sA);
            sB = fmaf(fmaxf(acc[rt][nt][2] + bb0, 0.f), ww0, sB);
            sB = fmaf(fmaxf(acc[rt][nt][3] + bb1, 0.f), ww1, sB);
        }
        sA += __shfl_xor_sync(0xffffffffu, sA, 1);
        sA += __shfl_xor_sync(0xffffffffu, sA, 2);
        sB += __shfl_xor_sync(0xffffffffu, sB, 1);
        sB += __shfl_xor_sync(0xffffffffu, sB, 2);
        if ((lane & 3) == 0) {
            int r = rt * 16 + (lane >> 2);
            s_red[w][r]     = sA;
            s_red[w][r + 8] = sB;
        }
    }
    __syncthreads();

    if (tid < TM) {
        int node = base + tid;
        if (node < N_NODES) {
            float logit = __ldg(b2);
            #pragma unroll
            for (int ww = 0; ww < 8; ++ww) logit += s_red[ww][tid];
            g_wnode[node] = 1.f / (1.f + expf(-logit));
        }
    }
}

// ---------------------------------------------------------------------------
// Aggregation: R10 form (prefetch variant regressed in R11).
// ---------------------------------------------------------------------------
__global__ __launch_bounds__(NTHR, 8)
void agg_kernel(float* __restrict__ out)
{
    const int warp = (blockIdx.x * NTHR + threadIdx.x) >> 5;
    const int lane = threadIdx.x & 31;
    if (warp >= N_NODES) return;

    const int s = g_start[warp];
    const int e = g_start[warp + 1];

    float acc[8] = {0.f, 0.f, 0.f, 0.f, 0.f, 0.f, 0.f, 0.f};
    float wsum = 0.f;

    for (int base = s; base < e; base += 32) {
        const int n = min(32, e - base);
        int   col = 0;
        float wv  = 0.f;
        if (lane < n) {
            col = g_scol[base + lane];
            wv  = __ldg(&g_wnode[col]);
        }
        for (int c = 0; c < n; ++c) {
            int   cc = __shfl_sync(0xffffffffu, col, c);
            float ww = __shfl_sync(0xffffffffu, wv,  c);
            const uint4* src = (const uint4*)(g_xh + (long long)cc * DIM);
            uint4 p = __ldg(src + lane);
            float2 f0 = __half22float2(*(const __half2*)&p.x);
            float2 f1 = __half22float2(*(const __half2*)&p.y);
            float2 f2 = __half22float2(*(const __half2*)&p.z);
            float2 f3 = __half22float2(*(const __half2*)&p.w);
            acc[0] = fmaf(ww, f0.x, acc[0]);
            acc[1] = fmaf(ww, f0.y, acc[1]);
            acc[2] = fmaf(ww, f1.x, acc[2]);
            acc[3] = fmaf(ww, f1.y, acc[3]);
            acc[4] = fmaf(ww, f2.x, acc[4]);
            acc[5] = fmaf(ww, f2.y, acc[5]);
            acc[6] = fmaf(ww, f3.x, acc[6]);
            acc[7] = fmaf(ww, f3.y, acc[7]);
            wsum += ww;
        }
    }

    float4* dst = (float4*)(out + (long long)warp * DIM) + lane * 2;
    if (e > s) {
        float inv = 1.f / fmaxf(wsum, 1e-12f);
        dst[0] = make_float4(acc[0] * inv, acc[1] * inv, acc[2] * inv, acc[3] * inv);
        dst[1] = make_float4(acc[4] * inv, acc[5] * inv, acc[6] * inv, acc[7] * inv);
    } else {
        float4 z = make_float4(0.f, 0.f, 0.f, 0.f);
        dst[0] = z;
        dst[1] = z;
    }
}

// ---------------------------------------------------------------------------
extern "C" void kernel_launch(void* const* d_in, const int* in_sizes, int n_in,
                              void* d_out, int out_size) {
    const float* x   = (const float*)d_in[0];
    const void*  ei  = d_in[1];
    const float* W1  = (const float*)d_in[2];
    const float* b1  = (const float*)d_in[3];
    const float* W2  = (const float*)d_in[4];
    const float* b2  = (const float*)d_in[5];
    float*       out = (float*)d_out;

    static cudaStream_t s_side = nullptr;
    static cudaEvent_t  ev_fork = nullptr, ev_join = nullptr;
    if (!s_side) {
        cudaStreamCreateWithFlags(&s_side, cudaStreamNonBlocking);
        cudaEventCreateWithFlags(&ev_fork, cudaEventDisableTiming);
        cudaEventCreateWithFlags(&ev_join, cudaEventDisableTiming);
        cudaFuncSetAttribute(node_weight_kernel,
                             cudaFuncAttributeMaxDynamicSharedMemorySize, NW_SMEM);
    }

    cudaEventRecord(ev_fork, 0);
    cudaStreamWaitEvent(s_side, ev_fork, 0);

    // side stream: fp16 mirror of x, then CSR build
    const int total4 = N_NODES * (DIM / 4);
    convert_x_kernel<<<(total4 + 255) / 256, 256, 0, s_side>>>((const float4*)x);
    detect_kernel<<<1, 1, 0, s_side>>>((const int*)ei);
    zero_cnt_kernel<<<(N_NODES + 255) / 256, 256, 0, s_side>>>();
    count_kernel<<<(N_EDGES + NTHR - 1) / NTHR, NTHR, 0, s_side>>>(ei);
    scan1_kernel<<<NB_SCAN, SCAN_B, 0, s_side>>>();
    scan2_kernel<<<1, 32, 0, s_side>>>();
    scan3_kernel<<<(N_NODES + 255) / 256, 256, 0, s_side>>>();
    fill_kernel<<<(N_EDGES + NTHR - 1) / NTHR, NTHR, 0, s_side>>>(ei);
    cudaEventRecord(ev_join, s_side);

    // main stream: B-fragment pack, then HMMA node weights (TM=128)
    prep_w1_pack_kernel<<<(HID * (DIM / 2) + 255) / 256, 256>>>(W1);
    const int nw_blocks = (N_NODES + TM - 1) / TM;   // 391
    node_weight_kernel<<<nw_blocks, NTHR, NW_SMEM>>>(x, b1, W2, b2);

    cudaStreamWaitEvent(0, ev_join, 0);
    const int agg_blocks = (N_NODES * 32 + NTHR - 1) / NTHR;  // 6250
    agg_kernel<<<agg_blocks, NTHR>>>(out);
}